// round 15
// baseline (speedup 1.0000x reference)
#include <cuda_runtime.h>
#include <cuda_fp16.h>
#include <cstdint>

#define NCLS 4
#define VMX 64
#define NF 28
#define HID 64
#define OUTF 768
#define NBINS (NCLS*VMX*NF)   // 7168
#define NMAX 100096
#define MTILE 128
#define NTILE 128

typedef unsigned long long ull;

// static scratch (no allocations allowed)
__device__ int   g_counts[NBINS];
__device__ float g_prob[NBINS];
__device__ __align__(16) __half g_hf[(size_t)NMAX * HID];   // h (fp16)
__device__ __align__(16) __half g_wf[OUTF * HID];           // W_fc (fp16)
__device__ __align__(16) __half g_wg[192 * 32];             // W_ih (i,g,o), K-padded
__device__ float g_bias2[192];                              // b_ih + b_hh (i,g,o)

// ---------------- prologue kernels ----------------
__global__ void prep_kernel(const float* __restrict__ W,
                            const float* __restrict__ Wih,
                            const float* __restrict__ bih,
                            const float* __restrict__ bhh) {
    int i = blockIdx.x * blockDim.x + threadIdx.x;
    if (i < NBINS) g_counts[i] = 0;
    if (i < OUTF * HID) g_wf[i] = __float2half(W[i]);
    if (i < 192 * 32) {
        int j = i >> 5, k = i & 31;
        int c = (j < 64) ? j : j + 64;   // skip f-gate rows
        g_wg[i] = (k < NF) ? __float2half(Wih[c * NF + k]) : __half(0);
    }
    if (i < 192) {
        int c = (i < 64) ? i : i + 64;
        g_bias2[i] = bih[c] + bhh[c];
    }
}

__global__ void hist_kernel(const float* __restrict__ VS,
                            const int* __restrict__ Level, int N) {
    __shared__ int s_counts[NBINS];
    for (int i = threadIdx.x; i < NBINS; i += blockDim.x) s_counts[i] = 0;
    __syncthreads();
    int stride = gridDim.x * blockDim.x;
    for (int r = blockIdx.x * blockDim.x + threadIdx.x; r < N; r += stride) {
        int lev = Level[r];
        int base = lev * VMX;
        const float4* vrow = (const float4*)(VS + (size_t)r * NF);
#pragma unroll
        for (int q = 0; q < 7; q++) {
            float4 v = vrow[q];
            atomicAdd(&s_counts[(base + (int)v.x) * NF + 4*q + 0], 1);
            atomicAdd(&s_counts[(base + (int)v.y) * NF + 4*q + 1], 1);
            atomicAdd(&s_counts[(base + (int)v.z) * NF + 4*q + 2], 1);
            atomicAdd(&s_counts[(base + (int)v.w) * NF + 4*q + 3], 1);
        }
    }
    __syncthreads();
    for (int i = threadIdx.x; i < NBINS; i += blockDim.x)
        if (s_counts[i]) atomicAdd(&g_counts[i], s_counts[i]);
}

__global__ void prob_kernel() {
    __shared__ float cls_sz[NCLS];
    int t = threadIdx.x;
    if (t < NCLS) cls_sz[t] = 0.0f;
    __syncthreads();
    atomicAdd(&cls_sz[t >> 6], (float)g_counts[t * NF]);
    __syncthreads();
    for (int j = t; j < NBINS; j += 256) {
        int cls = j / (VMX * NF);
        g_prob[j] = (float)g_counts[j] / cls_sz[cls];
    }
}

// ---------------- helpers ----------------
__device__ __forceinline__ float sig_t(float x) {      // sigmoid via MUFU.TANH
    return 0.5f * tanhf(0.5f * x) + 0.5f;
}
__device__ __forceinline__ uint32_t smem_u32(const void* p) {
    uint32_t a;
    asm("{ .reg .u64 t; cvta.to.shared.u64 t, %1; cvt.u32.u64 %0, t; }"
        : "=r"(a) : "l"(p));
    return a;
}
__device__ __forceinline__ void ldsm4(uint32_t addr, uint32_t* r) {
    asm volatile("ldmatrix.sync.aligned.m8n8.x4.shared.b16 {%0,%1,%2,%3}, [%4];"
        : "=r"(r[0]), "=r"(r[1]), "=r"(r[2]), "=r"(r[3]) : "r"(addr));
}
__device__ __forceinline__ void mma_f16(float* c, const uint32_t* a,
                                        uint32_t b0, uint32_t b1) {
    asm volatile(
        "mma.sync.aligned.m16n8k16.row.col.f32.f16.f16.f32 "
        "{%0,%1,%2,%3}, {%4,%5,%6,%7}, {%8,%9}, {%0,%1,%2,%3};"
        : "+f"(c[0]), "+f"(c[1]), "+f"(c[2]), "+f"(c[3])
        : "r"(a[0]), "r"(a[1]), "r"(a[2]), "r"(a[3]), "r"(b0), "r"(b1));
}

// ---------------- h kernel: MMA gates + in-register activations; copy blocks ----------------
// smem: A_s 2kc x 128 x 48 = 12288; B_s 2kc x 192 x 48 = 18432; bias 768
#define AKC 6144     // A per-kc block: 128*48
#define BKC 9216     // B per-kc block: 192*48
#define HB_OFF 12288
#define HBIAS_OFF 30720
#define HK_SMEM 31744

__global__ __launch_bounds__(256)
void h_kernel(const float* __restrict__ VS,
              const int* __restrict__ Level,
              const int* __restrict__ Depart,
              const float* __restrict__ CC,
              float* __restrict__ cc_out,
              float* __restrict__ lev_out,
              float* __restrict__ dep_out,
              int N)
{
    const int t = threadIdx.x;
    const int bid = blockIdx.x;
    const int row0 = (bid >> 1) * MTILE;
    if (row0 >= N) return;

    // ---- copy blocks: 128 CC rows, 8-deep pipelined ----
    if (bid & 1) {
        const float4* src = (const float4*)(CC + (size_t)row0 * OUTF);
        float4* dst = (float4*)(cc_out + (size_t)row0 * OUTF);
        if (row0 + MTILE <= N) {
#pragma unroll 1
            for (int it = 0; it < 12; it++) {
                int base = it * 2048 + t;
                float4 buf[8];
#pragma unroll
                for (int j = 0; j < 8; j++) buf[j] = src[base + j * 256];
#pragma unroll
                for (int j = 0; j < 8; j++) dst[base + j * 256] = buf[j];
            }
        } else {
            int total = (N - row0) * (OUTF / 4);
            for (int i = t; i < total; i += 256) dst[i] = src[i];
        }
        return;
    }

    // ---- compute blocks ----
    extern __shared__ char sm[];
    __shared__ int lev_s[MTILE];
    const uint32_t sb = smem_u32(sm);
    const int lane = t & 31;
    const int w = t >> 5;

    if (t < MTILE) {
        int r = row0 + t;
        int lv = (r < N) ? Level[r] : 0;
        lev_s[t] = lv;
        if (r < N) { lev_out[r] = (float)lv; dep_out[r] = (float)Depart[r]; }
    }
    // B fill: g_wg [192 cols][32 k] fp16
    for (int i = t; i < 768; i += 256) {
        int n = i >> 2, q = i & 3;
        int kc = q >> 1, hf = q & 1;
        *(uint4*)(sm + HB_OFF + kc * BKC + n * 48 + hf * 16) =
            ((const uint4*)(g_wg + n * 32))[q];
    }
    if (t < 192) ((float*)(sm + HBIAS_OFF))[t] = g_bias2[t];
    __syncthreads();

    // A fill: x = VS*prob as fp16, K padded to 32
    for (int i = t; i < MTILE * 16; i += 256) {
        int r = i >> 4, kp = i & 15;
        int k = kp * 2;
        float x0 = 0.0f, x1 = 0.0f;
        if (k < NF && row0 + r < N) {
            int lev = lev_s[r];
            float v0 = VS[(size_t)(row0 + r) * NF + k];
            float v1 = VS[(size_t)(row0 + r) * NF + k + 1];
            x0 = v0 * g_prob[(lev * VMX + (int)v0) * NF + k];
            x1 = v1 * g_prob[(lev * VMX + (int)v1) * NF + k + 1];
        }
        int kc = k >> 4, hf = (k >> 3) & 1;
        *(__half2*)(sm + kc * AKC + r * 48 + hf * 16 + (k & 7) * 2) =
            __floats2half2_rn(x0, x1);
    }
    __syncthreads();

    // MMA gates + in-register activations. warp w owns rows 16w..16w+15.
    {
        const int rowb = w * 16;
        const uint32_t a_lane_off =
            (uint32_t)((rowb + (lane & 15)) * 48 + ((lane & 16) ? 16 : 0));
        uint32_t A0[4], A1[4];
        ldsm4(sb + a_lane_off, A0);
        ldsm4(sb + AKC + a_lane_off, A1);

        const uint32_t b_base = sb + (uint32_t)(HB_OFF + ((lane >> 4) & 1) * BKC
                                + (lane & 7) * 48 + ((lane & 8) ? 16 : 0));
        const float* bs = (const float*)(sm + HBIAS_OFF);
        const int cb = (lane & 3) * 2;
        const int r_lo = row0 + rowb + (lane >> 2);
        const int r_hi = r_lo + 8;

#pragma unroll
        for (int g8 = 0; g8 < 8; g8++) {
            uint32_t Bi[4], Bg[4], Bo[4];
            ldsm4(b_base + (uint32_t)((g8 * 8) * 48), Bi);
            ldsm4(b_base + (uint32_t)((64 + g8 * 8) * 48), Bg);
            ldsm4(b_base + (uint32_t)((128 + g8 * 8) * 48), Bo);

            int u0 = g8 * 8 + cb;
            float bi0 = bs[u0],       bi1 = bs[u0 + 1];
            float bg0 = bs[64 + u0],  bg1 = bs[64 + u0 + 1];
            float bo0 = bs[128 + u0], bo1 = bs[128 + u0 + 1];
            float ai[4] = {bi0, bi1, bi0, bi1};
            float ag[4] = {bg0, bg1, bg0, bg1};
            float ao[4] = {bo0, bo1, bo0, bo1};

            mma_f16(ai, A0, Bi[0], Bi[1]);  mma_f16(ai, A1, Bi[2], Bi[3]);
            mma_f16(ag, A0, Bg[0], Bg[1]);  mma_f16(ag, A1, Bg[2], Bg[3]);
            mma_f16(ao, A0, Bo[0], Bo[1]);  mma_f16(ao, A1, Bo[2], Bo[3]);

            float h0 = sig_t(ao[0]) * tanhf(sig_t(ai[0]) * tanhf(ag[0]));
            float h1 = sig_t(ao[1]) * tanhf(sig_t(ai[1]) * tanhf(ag[1]));
            float h2 = sig_t(ao[2]) * tanhf(sig_t(ai[2]) * tanhf(ag[2]));
            float h3 = sig_t(ao[3]) * tanhf(sig_t(ai[3]) * tanhf(ag[3]));

            if (r_lo < N)
                *(__half2*)(g_hf + (size_t)r_lo * HID + u0) = __floats2half2_rn(h0, h1);
            if (r_hi < N)
                *(__half2*)(g_hf + (size_t)r_hi * HID + u0) = __floats2half2_rn(h2, h3);
        }
    }
}

// ---------------- gemm kernel: 64-row tiles, 128 threads, high occupancy ----------------
// smem: A[kc(4)][r(64)][48B] = 12288; B[kc(4)][n(128)][48B] = 24576; bias 512
#define MT2 64
#define AK2 3072     // 64*48
#define BK2 6144     // 128*48
#define B2_OFF 12288
#define S2_BIAS 36864
#define GEMM_SMEM 37376

__global__ __launch_bounds__(128)
void gemm_kernel(const float* __restrict__ b_fc,
                 float* __restrict__ vs_out,
                 int N)
{
    extern __shared__ char sm[];
    const int t = threadIdx.x;
    const int bid = blockIdx.x;
    const int sub = bid % 6;
    const int row0 = (bid / 6) * MT2;

    const int lane = t & 31;
    const int wm = t >> 5;            // 0..3, 16 rows each
    const int ctb = sub * NTILE;
    const uint32_t sb = smem_u32(sm);

    // bias (128 floats)
    if (t < 32) ((float4*)(sm + S2_BIAS))[t] = ((const float4*)(b_fc + ctb))[t];

    // A fill: 64 rows x 8 chunks = 512 items
#pragma unroll
    for (int j = 0; j < 4; j++) {
        int i = t + j * 128;
        int r = i >> 3, q = i & 7;
        int kc = q >> 1, hf = q & 1;
        uint4 v = make_uint4(0, 0, 0, 0);
        if (row0 + r < N)
            v = ((const uint4*)(g_hf + (size_t)(row0 + r) * HID))[q];
        *(uint4*)(sm + kc * AK2 + r * 48 + hf * 16) = v;
    }
    // B fill: 128 rows x 8 chunks = 1024 items (L2-resident g_wf)
#pragma unroll
    for (int j = 0; j < 8; j++) {
        int i = t + j * 128;
        int n = i >> 3, q = i & 7;
        int kc = q >> 1, hf = q & 1;
        *(uint4*)(sm + B2_OFF + kc * BK2 + n * 48 + hf * 16) =
            ((const uint4*)(g_wf + (size_t)(ctb + n) * HID))[q];
    }
    __syncthreads();

    // all 4 A fragments up front
    const int rowb = wm * 16;
    const uint32_t a_lane_off = (uint32_t)((rowb + (lane & 15)) * 48 + ((lane & 16) ? 16 : 0));
    uint32_t A[4][4];
#pragma unroll
    for (int kc = 0; kc < 4; kc++)
        ldsm4(sb + kc * AK2 + a_lane_off, A[kc]);

    const uint32_t b_base = sb + (uint32_t)(B2_OFF + ((lane >> 4) & 1) * BK2
                            + (lane & 7) * 48 + ((lane & 8) ? 16 : 0));
    const float* bs = (const float*)(sm + S2_BIAS);
    const int cb = (lane & 3) * 2;
    const int r_lo = row0 + rowb + (lane >> 2);
    const int r_hi = r_lo + 8;

    // per n-tile: B loads + 4 MMA + immediate store (stores spread across loop)
#pragma unroll
    for (int nt = 0; nt < 16; nt++) {
        float acc[4];
        {
            float b0 = bs[nt * 8 + cb], b1 = bs[nt * 8 + cb + 1];
            acc[0] = b0; acc[1] = b1; acc[2] = b0; acc[3] = b1;
        }
        uint32_t B[4];
        uint32_t boff = (uint32_t)(nt * 8 * 48);
        ldsm4(b_base + boff, B);                 // kc 0,1
        mma_f16(acc, A[0], B[0], B[1]);
        mma_f16(acc, A[1], B[2], B[3]);
        ldsm4(b_base + 2 * BK2 + boff, B);       // kc 2,3
        mma_f16(acc, A[2], B[0], B[1]);
        mma_f16(acc, A[3], B[2], B[3]);

        if (r_lo < N)
            *(float2*)(vs_out + (size_t)r_lo * OUTF + ctb + cb + nt * 8) =
                make_float2(acc[0], acc[1]);
        if (r_hi < N)
            *(float2*)(vs_out + (size_t)r_hi * OUTF + ctb + cb + nt * 8) =
                make_float2(acc[2], acc[3]);
    }
}

extern "C" void kernel_launch(void* const* d_in, const int* in_sizes, int n_in,
                              void* d_out, int out_size) {
    const float* VS     = (const float*)d_in[0];
    const float* CC     = (const float*)d_in[1];
    const int*   Level  = (const int*)d_in[2];
    const int*   Depart = (const int*)d_in[3];
    const float* W_ih   = (const float*)d_in[4];
    // d_in[5] = W_hh, unused (h0 = 0)
    const float* b_ih   = (const float*)d_in[6];
    const float* b_hh   = (const float*)d_in[7];
    const float* W_fc   = (const float*)d_in[8];
    const float* b_fc   = (const float*)d_in[9];

    int N = in_sizes[0] / NF;

    float* out = (float*)d_out;
    float* cc_out  = out;
    float* vs_out  = out + (size_t)N * OUTF;
    float* lev_out = out + (size_t)2 * N * OUTF;
    float* dep_out = lev_out + N;

    static int attr_set = 0;
    if (!attr_set) {
        cudaFuncSetAttribute(h_kernel,
                             cudaFuncAttributeMaxDynamicSharedMemorySize, HK_SMEM);
        cudaFuncSetAttribute(gemm_kernel,
                             cudaFuncAttributeMaxDynamicSharedMemorySize, GEMM_SMEM);
        attr_set = 1;
    }

    prep_kernel<<<(OUTF * HID + 255) / 256, 256>>>(W_fc, W_ih, b_ih, b_hh);
    hist_kernel<<<148, 256>>>(VS, Level, N);
    prob_kernel<<<1, 256>>>();
    int nstrip = (N + MTILE - 1) / MTILE;
    h_kernel<<<nstrip * 2, 256, HK_SMEM>>>(
        VS, Level, Depart, CC, cc_out, lev_out, dep_out, N);
    int nstrip2 = (N + MT2 - 1) / MT2;
    gemm_kernel<<<nstrip2 * 6, 128, GEMM_SMEM>>>(b_fc, vs_out, N);
}

// round 16
// speedup vs baseline: 1.0518x; 1.0518x over previous
#include <cuda_runtime.h>
#include <cuda_fp16.h>
#include <cstdint>

#define NCLS 4
#define VMX 64
#define NF 28
#define HID 64
#define OUTF 768
#define NBINS (NCLS*VMX*NF)   // 7168
#define NMAX 100096
#define MTILE 128
#define NTILE 128

typedef unsigned long long ull;

// static scratch (no allocations allowed)
__device__ int   g_counts[NBINS];      // zero-init at load; re-zeroed each run
__device__ int   g_done;               // ticket counter, re-zeroed each run
__device__ float g_prob[NBINS];
__device__ __align__(16) __half g_hf[(size_t)NMAX * HID];   // h (fp16)
__device__ __align__(16) __half g_wf[OUTF * HID];           // W_fc (fp16)
__device__ __align__(16) __half g_wg[192 * 32];             // W_ih (i,g,o), K-padded
__device__ float g_bias2[192];                              // b_ih + b_hh (i,g,o)

// ---------------- fused prologue: conversions + histogram + prob (last block) ----------------
#define HIST_BLOCKS 148

__global__ void hist_all_kernel(const float* __restrict__ VS,
                                const int* __restrict__ Level,
                                const float* __restrict__ W,
                                const float* __restrict__ Wih,
                                const float* __restrict__ bih,
                                const float* __restrict__ bhh,
                                int N) {
    __shared__ int s_counts[NBINS];
    __shared__ int is_last;
    const int t = threadIdx.x;
    const int gstride = HIST_BLOCKS * 256;
    const int gtid = blockIdx.x * 256 + t;

    // ---- weight conversions (grid-strided, overlaps histogram) ----
    for (int i = gtid; i < OUTF * HID; i += gstride)
        g_wf[i] = __float2half(W[i]);
    for (int i = gtid; i < 192 * 32; i += gstride) {
        int j = i >> 5, k = i & 31;
        int c = (j < 64) ? j : j + 64;   // skip f-gate rows
        g_wg[i] = (k < NF) ? __float2half(Wih[c * NF + k]) : __half(0);
    }
    for (int i = gtid; i < 192; i += gstride) {
        int c = (i < 64) ? i : i + 64;
        g_bias2[i] = bih[c] + bhh[c];
    }

    // ---- histogram ----
    for (int i = t; i < NBINS; i += 256) s_counts[i] = 0;
    __syncthreads();
    for (int r = gtid; r < N; r += gstride) {
        int lev = Level[r];
        int base = lev * VMX;
        const float4* vrow = (const float4*)(VS + (size_t)r * NF);
#pragma unroll
        for (int q = 0; q < 7; q++) {
            float4 v = vrow[q];
            atomicAdd(&s_counts[(base + (int)v.x) * NF + 4*q + 0], 1);
            atomicAdd(&s_counts[(base + (int)v.y) * NF + 4*q + 1], 1);
            atomicAdd(&s_counts[(base + (int)v.z) * NF + 4*q + 2], 1);
            atomicAdd(&s_counts[(base + (int)v.w) * NF + 4*q + 3], 1);
        }
    }
    __syncthreads();
    for (int i = t; i < NBINS; i += 256)
        if (s_counts[i]) atomicAdd(&g_counts[i], s_counts[i]);

    // ---- last block computes prob, then resets counters for next replay ----
    __threadfence();
    if (t == 0) {
        int v = atomicAdd(&g_done, 1);
        is_last = (v == HIST_BLOCKS - 1);
    }
    __syncthreads();
    if (is_last) {
        __shared__ float cls_sz[NCLS];
        if (t < NCLS) cls_sz[t] = 0.0f;
        __syncthreads();
        atomicAdd(&cls_sz[t >> 6], (float)g_counts[t * NF]);
        __syncthreads();
        for (int j = t; j < NBINS; j += 256) {
            int cls = j / (VMX * NF);
            g_prob[j] = (float)g_counts[j] / cls_sz[cls];
        }
        __syncthreads();
        for (int j = t; j < NBINS; j += 256) g_counts[j] = 0;
        if (t == 0) g_done = 0;
    }
}

// ---------------- helpers ----------------
__device__ __forceinline__ float sig_t(float x) {      // sigmoid via MUFU.TANH
    return 0.5f * tanhf(0.5f * x) + 0.5f;
}
__device__ __forceinline__ uint32_t smem_u32(const void* p) {
    uint32_t a;
    asm("{ .reg .u64 t; cvta.to.shared.u64 t, %1; cvt.u32.u64 %0, t; }"
        : "=r"(a) : "l"(p));
    return a;
}
__device__ __forceinline__ void ldsm4(uint32_t addr, uint32_t* r) {
    asm volatile("ldmatrix.sync.aligned.m8n8.x4.shared.b16 {%0,%1,%2,%3}, [%4];"
        : "=r"(r[0]), "=r"(r[1]), "=r"(r[2]), "=r"(r[3]) : "r"(addr));
}
__device__ __forceinline__ void mma_f16(float* c, const uint32_t* a,
                                        uint32_t b0, uint32_t b1) {
    asm volatile(
        "mma.sync.aligned.m16n8k16.row.col.f32.f16.f16.f32 "
        "{%0,%1,%2,%3}, {%4,%5,%6,%7}, {%8,%9}, {%0,%1,%2,%3};"
        : "+f"(c[0]), "+f"(c[1]), "+f"(c[2]), "+f"(c[3])
        : "r"(a[0]), "r"(a[1]), "r"(a[2]), "r"(a[3]), "r"(b0), "r"(b1));
}

// ---------------- h kernel: MMA gates + in-register activations; copy blocks ----------------
// smem: A_s 2kc x 128 x 48 = 12288; B_s 2kc x 192 x 48 = 18432; bias 768
#define AKC 6144     // A per-kc block: 128*48
#define BKC 9216     // B per-kc block: 192*48
#define HB_OFF 12288
#define HBIAS_OFF 30720
#define HK_SMEM 31744

__global__ __launch_bounds__(256)
void h_kernel(const float* __restrict__ VS,
              const int* __restrict__ Level,
              const int* __restrict__ Depart,
              const float* __restrict__ CC,
              float* __restrict__ cc_out,
              float* __restrict__ lev_out,
              float* __restrict__ dep_out,
              int N)
{
    const int t = threadIdx.x;
    const int bid = blockIdx.x;
    const int row0 = (bid >> 1) * MTILE;
    if (row0 >= N) return;

    // ---- copy blocks: 128 CC rows, 8-deep pipelined ----
    if (bid & 1) {
        const float4* src = (const float4*)(CC + (size_t)row0 * OUTF);
        float4* dst = (float4*)(cc_out + (size_t)row0 * OUTF);
        if (row0 + MTILE <= N) {
#pragma unroll 1
            for (int it = 0; it < 12; it++) {
                int base = it * 2048 + t;
                float4 buf[8];
#pragma unroll
                for (int j = 0; j < 8; j++) buf[j] = src[base + j * 256];
#pragma unroll
                for (int j = 0; j < 8; j++) dst[base + j * 256] = buf[j];
            }
        } else {
            int total = (N - row0) * (OUTF / 4);
            for (int i = t; i < total; i += 256) dst[i] = src[i];
        }
        return;
    }

    // ---- compute blocks ----
    extern __shared__ char sm[];
    __shared__ int lev_s[MTILE];
    const uint32_t sb = smem_u32(sm);
    const int lane = t & 31;
    const int w = t >> 5;

    if (t < MTILE) {
        int r = row0 + t;
        int lv = (r < N) ? Level[r] : 0;
        lev_s[t] = lv;
        if (r < N) { lev_out[r] = (float)lv; dep_out[r] = (float)Depart[r]; }
    }
    // B fill: g_wg [192 cols][32 k] fp16
    for (int i = t; i < 768; i += 256) {
        int n = i >> 2, q = i & 3;
        int kc = q >> 1, hf = q & 1;
        *(uint4*)(sm + HB_OFF + kc * BKC + n * 48 + hf * 16) =
            ((const uint4*)(g_wg + n * 32))[q];
    }
    if (t < 192) ((float*)(sm + HBIAS_OFF))[t] = g_bias2[t];
    __syncthreads();

    // A fill: x = VS*prob as fp16, K padded to 32
    for (int i = t; i < MTILE * 16; i += 256) {
        int r = i >> 4, kp = i & 15;
        int k = kp * 2;
        float x0 = 0.0f, x1 = 0.0f;
        if (k < NF && row0 + r < N) {
            int lev = lev_s[r];
            float v0 = VS[(size_t)(row0 + r) * NF + k];
            float v1 = VS[(size_t)(row0 + r) * NF + k + 1];
            x0 = v0 * g_prob[(lev * VMX + (int)v0) * NF + k];
            x1 = v1 * g_prob[(lev * VMX + (int)v1) * NF + k + 1];
        }
        int kc = k >> 4, hf = (k >> 3) & 1;
        *(__half2*)(sm + kc * AKC + r * 48 + hf * 16 + (k & 7) * 2) =
            __floats2half2_rn(x0, x1);
    }
    __syncthreads();

    // MMA gates + in-register activations. warp w owns rows 16w..16w+15.
    {
        const int rowb = w * 16;
        const uint32_t a_lane_off =
            (uint32_t)((rowb + (lane & 15)) * 48 + ((lane & 16) ? 16 : 0));
        uint32_t A0[4], A1[4];
        ldsm4(sb + a_lane_off, A0);
        ldsm4(sb + AKC + a_lane_off, A1);

        const uint32_t b_base = sb + (uint32_t)(HB_OFF + ((lane >> 4) & 1) * BKC
                                + (lane & 7) * 48 + ((lane & 8) ? 16 : 0));
        const float* bs = (const float*)(sm + HBIAS_OFF);
        const int cb = (lane & 3) * 2;
        const int r_lo = row0 + rowb + (lane >> 2);
        const int r_hi = r_lo + 8;

#pragma unroll
        for (int g8 = 0; g8 < 8; g8++) {
            uint32_t Bi[4], Bg[4], Bo[4];
            ldsm4(b_base + (uint32_t)((g8 * 8) * 48), Bi);
            ldsm4(b_base + (uint32_t)((64 + g8 * 8) * 48), Bg);
            ldsm4(b_base + (uint32_t)((128 + g8 * 8) * 48), Bo);

            int u0 = g8 * 8 + cb;
            float bi0 = bs[u0],       bi1 = bs[u0 + 1];
            float bg0 = bs[64 + u0],  bg1 = bs[64 + u0 + 1];
            float bo0 = bs[128 + u0], bo1 = bs[128 + u0 + 1];
            float ai[4] = {bi0, bi1, bi0, bi1};
            float ag[4] = {bg0, bg1, bg0, bg1};
            float ao[4] = {bo0, bo1, bo0, bo1};

            mma_f16(ai, A0, Bi[0], Bi[1]);  mma_f16(ai, A1, Bi[2], Bi[3]);
            mma_f16(ag, A0, Bg[0], Bg[1]);  mma_f16(ag, A1, Bg[2], Bg[3]);
            mma_f16(ao, A0, Bo[0], Bo[1]);  mma_f16(ao, A1, Bo[2], Bo[3]);

            float h0 = sig_t(ao[0]) * tanhf(sig_t(ai[0]) * tanhf(ag[0]));
            float h1 = sig_t(ao[1]) * tanhf(sig_t(ai[1]) * tanhf(ag[1]));
            float h2 = sig_t(ao[2]) * tanhf(sig_t(ai[2]) * tanhf(ag[2]));
            float h3 = sig_t(ao[3]) * tanhf(sig_t(ai[3]) * tanhf(ag[3]));

            if (r_lo < N)
                *(__half2*)(g_hf + (size_t)r_lo * HID + u0) = __floats2half2_rn(h0, h1);
            if (r_hi < N)
                *(__half2*)(g_hf + (size_t)r_hi * HID + u0) = __floats2half2_rn(h2, h3);
        }
    }
}

// ---------------- gemm kernel: fp16 mma.sync (round-13 proven version) ----------------
// smem: A[kc(4)][r(128)][48B], B[kc(4)][n(128)][48B], bias
#define KCB 6144    // 128*48
#define A_OFF 0
#define B_OFF 24576
#define S_BIAS 49152
#define GEMM_SMEM 49664

__global__ __launch_bounds__(256, 2)
void gemm_kernel(const float* __restrict__ b_fc,
                 float* __restrict__ vs_out,
                 int N)
{
    extern __shared__ char sm[];
    const int t = threadIdx.x;
    const int bid = blockIdx.x;
    const int sub = bid % 6;
    const int row0 = (bid / 6) * MTILE;

    const int lane = t & 31;
    const int wm = t >> 5;
    const int ctb = sub * NTILE;
    const uint32_t sb = smem_u32(sm);

    // bias
    if (t < 32) ((float4*)(sm + S_BIAS))[t] = ((const float4*)(b_fc + ctb))[t];

    // A fill
#pragma unroll
    for (int j = 0; j < 4; j++) {
        int i = t + j * 256;
        int r = i >> 3, q = i & 7;
        int kc = q >> 1, hf = q & 1;
        uint4 v = make_uint4(0, 0, 0, 0);
        if (row0 + r < N)
            v = ((const uint4*)(g_hf + (size_t)(row0 + r) * HID))[q];
        *(uint4*)(sm + A_OFF + kc * KCB + r * 48 + hf * 16) = v;
    }
    // B fill
#pragma unroll
    for (int j = 0; j < 4; j++) {
        int i = t + j * 256;
        int n = i >> 3, q = i & 7;
        int kc = q >> 1, hf = q & 1;
        *(uint4*)(sm + B_OFF + kc * KCB + n * 48 + hf * 16) =
            ((const uint4*)(g_wf + (size_t)(ctb + n) * HID))[q];
    }
    __syncthreads();

    float acc[16][4];
    {
        const float* bs = (const float*)(sm + S_BIAS);
        int cb = (lane & 3) * 2;
#pragma unroll
        for (int nt = 0; nt < 16; nt++) {
            float b0 = bs[nt * 8 + cb], b1 = bs[nt * 8 + cb + 1];
            acc[nt][0] = b0; acc[nt][1] = b1; acc[nt][2] = b0; acc[nt][3] = b1;
        }
    }

    const int rowb = wm * 16;
    const uint32_t a_lane_off = (uint32_t)((rowb + (lane & 15)) * 48 + ((lane & 16) ? 16 : 0));
    const uint32_t b_row_off  = (uint32_t)((lane & 7) * 48 + ((lane & 8) ? 16 : 0));
    const uint32_t b_kc_sel   = (uint32_t)(((lane >> 4) & 1) * KCB);

#pragma unroll
    for (int p = 0; p < 2; p++) {
        uint32_t A[2][4];
#pragma unroll
        for (int j = 0; j < 2; j++)
            ldsm4(sb + A_OFF + (2 * p + j) * KCB + a_lane_off, A[j]);
#pragma unroll
        for (int nt = 0; nt < 16; nt++) {
            uint32_t B[4];
            uint32_t boff = 2 * p * KCB + b_kc_sel + (uint32_t)(nt * 8 * 48) + b_row_off;
            ldsm4(sb + B_OFF + boff, B);
            mma_f16(acc[nt], A[0], B[0], B[1]);
            mma_f16(acc[nt], A[1], B[2], B[3]);
        }
    }

    {
        int r_lo = row0 + rowb + (lane >> 2);
        int r_hi = r_lo + 8;
        int cb = ctb + (lane & 3) * 2;
#pragma unroll
        for (int nt = 0; nt < 16; nt++) {
            if (r_lo < N)
                *(float2*)(vs_out + (size_t)r_lo * OUTF + cb + nt * 8) =
                    make_float2(acc[nt][0], acc[nt][1]);
            if (r_hi < N)
                *(float2*)(vs_out + (size_t)r_hi * OUTF + cb + nt * 8) =
                    make_float2(acc[nt][2], acc[nt][3]);
        }
    }
}

extern "C" void kernel_launch(void* const* d_in, const int* in_sizes, int n_in,
                              void* d_out, int out_size) {
    const float* VS     = (const float*)d_in[0];
    const float* CC     = (const float*)d_in[1];
    const int*   Level  = (const int*)d_in[2];
    const int*   Depart = (const int*)d_in[3];
    const float* W_ih   = (const float*)d_in[4];
    // d_in[5] = W_hh, unused (h0 = 0)
    const float* b_ih   = (const float*)d_in[6];
    const float* b_hh   = (const float*)d_in[7];
    const float* W_fc   = (const float*)d_in[8];
    const float* b_fc   = (const float*)d_in[9];

    int N = in_sizes[0] / NF;

    float* out = (float*)d_out;
    float* cc_out  = out;
    float* vs_out  = out + (size_t)N * OUTF;
    float* lev_out = out + (size_t)2 * N * OUTF;
    float* dep_out = lev_out + N;

    static int attr_set = 0;
    if (!attr_set) {
        cudaFuncSetAttribute(h_kernel,
                             cudaFuncAttributeMaxDynamicSharedMemorySize, HK_SMEM);
        cudaFuncSetAttribute(gemm_kernel,
                             cudaFuncAttributeMaxDynamicSharedMemorySize, GEMM_SMEM);
        attr_set = 1;
    }

    hist_all_kernel<<<HIST_BLOCKS, 256>>>(VS, Level, W_fc, W_ih, b_ih, b_hh, N);
    int nstrip = (N + MTILE - 1) / MTILE;
    h_kernel<<<nstrip * 2, 256, HK_SMEM>>>(
        VS, Level, Depart, CC, cc_out, lev_out, dep_out, N);
    gemm_kernel<<<nstrip * 6, 256, GEMM_SMEM>>>(b_fc, vs_out, N);
}

// round 17
// speedup vs baseline: 1.0809x; 1.0276x over previous
#include <cuda_runtime.h>
#include <cuda_fp16.h>
#include <cstdint>

#define NCLS 4
#define VMX 64
#define NF 28
#define HID 64
#define OUTF 768
#define NBINS (NCLS*VMX*NF)   // 7168
#define NMAX 100096
#define MTILE 128
#define NTILE 128

typedef unsigned long long ull;

// static scratch (no allocations allowed)
__device__ int   g_counts[NBINS];      // zero-init at load; re-zeroed each run
__device__ int   g_done;               // ticket counter, re-zeroed each run
__device__ float g_prob[NBINS];
__device__ __align__(16) __half g_hf[(size_t)NMAX * HID];   // h (fp16)
__device__ __align__(16) __half g_wf[OUTF * HID];           // W_fc (fp16)
__device__ __align__(16) __half g_wg[192 * 32];             // W_ih (i,g,o), K-padded
__device__ float g_bias2[192];                              // b_ih + b_hh (i,g,o)

// ---------------- fused prologue: conversions + histogram + prob (last block) ----------------
#define HIST_BLOCKS 296

__global__ void hist_all_kernel(const float* __restrict__ VS,
                                const int* __restrict__ Level,
                                const float* __restrict__ W,
                                const float* __restrict__ Wih,
                                const float* __restrict__ bih,
                                const float* __restrict__ bhh,
                                int N) {
    __shared__ int s_counts[NBINS];
    __shared__ int is_last;
    const int t = threadIdx.x;
    const int gstride = HIST_BLOCKS * 256;
    const int gtid = blockIdx.x * 256 + t;

    // ---- weight conversions (grid-strided, overlaps histogram) ----
    for (int i = gtid; i < OUTF * HID; i += gstride)
        g_wf[i] = __float2half(W[i]);
    for (int i = gtid; i < 192 * 32; i += gstride) {
        int j = i >> 5, k = i & 31;
        int c = (j < 64) ? j : j + 64;   // skip f-gate rows
        g_wg[i] = (k < NF) ? __float2half(Wih[c * NF + k]) : __half(0);
    }
    for (int i = gtid; i < 192; i += gstride) {
        int c = (i < 64) ? i : i + 64;
        g_bias2[i] = bih[c] + bhh[c];
    }

    // ---- histogram ----
    for (int i = t; i < NBINS; i += 256) s_counts[i] = 0;
    __syncthreads();
    for (int r = gtid; r < N; r += gstride) {
        int lev = Level[r];
        int base = lev * VMX;
        const float4* vrow = (const float4*)(VS + (size_t)r * NF);
#pragma unroll
        for (int q = 0; q < 7; q++) {
            float4 v = vrow[q];
            atomicAdd(&s_counts[(base + (int)v.x) * NF + 4*q + 0], 1);
            atomicAdd(&s_counts[(base + (int)v.y) * NF + 4*q + 1], 1);
            atomicAdd(&s_counts[(base + (int)v.z) * NF + 4*q + 2], 1);
            atomicAdd(&s_counts[(base + (int)v.w) * NF + 4*q + 3], 1);
        }
    }
    __syncthreads();
    for (int i = t; i < NBINS; i += 256)
        if (s_counts[i]) atomicAdd(&g_counts[i], s_counts[i]);

    // ---- last block computes prob, then resets counters for next replay ----
    __threadfence();
    if (t == 0) {
        int v = atomicAdd(&g_done, 1);
        is_last = (v == HIST_BLOCKS - 1);
    }
    __syncthreads();
    if (is_last) {
        __shared__ float cls_sz[NCLS];
        if (t < NCLS) cls_sz[t] = 0.0f;
        __syncthreads();
        atomicAdd(&cls_sz[t >> 6], (float)g_counts[t * NF]);
        __syncthreads();
        for (int j = t; j < NBINS; j += 256) {
            int cls = j / (VMX * NF);
            g_prob[j] = (float)g_counts[j] / cls_sz[cls];
        }
        __syncthreads();
        for (int j = t; j < NBINS; j += 256) g_counts[j] = 0;
        if (t == 0) g_done = 0;
    }
}

// ---------------- helpers ----------------
__device__ __forceinline__ float sig_t(float x) {      // sigmoid via MUFU.TANH
    return 0.5f * tanhf(0.5f * x) + 0.5f;
}
__device__ __forceinline__ uint32_t smem_u32(const void* p) {
    uint32_t a;
    asm("{ .reg .u64 t; cvta.to.shared.u64 t, %1; cvt.u32.u64 %0, t; }"
        : "=r"(a) : "l"(p));
    return a;
}
__device__ __forceinline__ void ldsm4(uint32_t addr, uint32_t* r) {
    asm volatile("ldmatrix.sync.aligned.m8n8.x4.shared.b16 {%0,%1,%2,%3}, [%4];"
        : "=r"(r[0]), "=r"(r[1]), "=r"(r[2]), "=r"(r[3]) : "r"(addr));
}
__device__ __forceinline__ void mma_f16(float* c, const uint32_t* a,
                                        uint32_t b0, uint32_t b1) {
    asm volatile(
        "mma.sync.aligned.m16n8k16.row.col.f32.f16.f16.f32 "
        "{%0,%1,%2,%3}, {%4,%5,%6,%7}, {%8,%9}, {%0,%1,%2,%3};"
        : "+f"(c[0]), "+f"(c[1]), "+f"(c[2]), "+f"(c[3])
        : "r"(a[0]), "r"(a[1]), "r"(a[2]), "r"(a[3]), "r"(b0), "r"(b1));
}

// ---------------- h kernel: MMA gates + in-register activations; even-strip copy ----------------
// group g: bid%3==2 -> copy even strip 2g; else compute strip 2g + (bid%3)
// smem: A_s 2kc x 128 x 48 = 12288; B_s 2kc x 192 x 48 = 18432; bias 768
#define AKC 6144     // A per-kc block: 128*48
#define BKC 9216     // B per-kc block: 192*48
#define HB_OFF 12288
#define HBIAS_OFF 30720
#define HK_SMEM 31744

__global__ __launch_bounds__(256)
void h_kernel(const float* __restrict__ VS,
              const int* __restrict__ Level,
              const int* __restrict__ Depart,
              const float* __restrict__ CC,
              float* __restrict__ cc_out,
              float* __restrict__ lev_out,
              float* __restrict__ dep_out,
              int N)
{
    const int t = threadIdx.x;
    const int bid = blockIdx.x;
    const int g = bid / 3, r3 = bid % 3;

    // ---- copy blocks: even strip (128 CC rows), 8-deep pipelined ----
    if (r3 == 2) {
        int row0 = (2 * g) * MTILE;
        if (row0 >= N) return;
        const float4* src = (const float4*)(CC + (size_t)row0 * OUTF);
        float4* dst = (float4*)(cc_out + (size_t)row0 * OUTF);
        if (row0 + MTILE <= N) {
#pragma unroll 1
            for (int it = 0; it < 12; it++) {
                int base = it * 2048 + t;
                float4 buf[8];
#pragma unroll
                for (int j = 0; j < 8; j++) buf[j] = src[base + j * 256];
#pragma unroll
                for (int j = 0; j < 8; j++) dst[base + j * 256] = buf[j];
            }
        } else {
            int total = (N - row0) * (OUTF / 4);
            for (int i = t; i < total; i += 256) dst[i] = src[i];
        }
        return;
    }

    // ---- compute blocks ----
    const int row0 = (2 * g + r3) * MTILE;
    if (row0 >= N) return;

    extern __shared__ char sm[];
    __shared__ int lev_s[MTILE];
    const uint32_t sb = smem_u32(sm);
    const int lane = t & 31;
    const int w = t >> 5;

    if (t < MTILE) {
        int r = row0 + t;
        int lv = (r < N) ? Level[r] : 0;
        lev_s[t] = lv;
        if (r < N) { lev_out[r] = (float)lv; dep_out[r] = (float)Depart[r]; }
    }
    // B fill: g_wg [192 cols][32 k] fp16
    for (int i = t; i < 768; i += 256) {
        int n = i >> 2, q = i & 3;
        int kc = q >> 1, hf = q & 1;
        *(uint4*)(sm + HB_OFF + kc * BKC + n * 48 + hf * 16) =
            ((const uint4*)(g_wg + n * 32))[q];
    }
    if (t < 192) ((float*)(sm + HBIAS_OFF))[t] = g_bias2[t];
    __syncthreads();

    // A fill: x = VS*prob as fp16, K padded to 32
    for (int i = t; i < MTILE * 16; i += 256) {
        int r = i >> 4, kp = i & 15;
        int k = kp * 2;
        float x0 = 0.0f, x1 = 0.0f;
        if (k < NF && row0 + r < N) {
            int lev = lev_s[r];
            float v0 = VS[(size_t)(row0 + r) * NF + k];
            float v1 = VS[(size_t)(row0 + r) * NF + k + 1];
            x0 = v0 * g_prob[(lev * VMX + (int)v0) * NF + k];
            x1 = v1 * g_prob[(lev * VMX + (int)v1) * NF + k + 1];
        }
        int kc = k >> 4, hf = (k >> 3) & 1;
        *(__half2*)(sm + kc * AKC + r * 48 + hf * 16 + (k & 7) * 2) =
            __floats2half2_rn(x0, x1);
    }
    __syncthreads();

    // MMA gates + in-register activations. warp w owns rows 16w..16w+15.
    {
        const int rowb = w * 16;
        const uint32_t a_lane_off =
            (uint32_t)((rowb + (lane & 15)) * 48 + ((lane & 16) ? 16 : 0));
        uint32_t A0[4], A1[4];
        ldsm4(sb + a_lane_off, A0);
        ldsm4(sb + AKC + a_lane_off, A1);

        const uint32_t b_base = sb + (uint32_t)(HB_OFF + ((lane >> 4) & 1) * BKC
                                + (lane & 7) * 48 + ((lane & 8) ? 16 : 0));
        const float* bs = (const float*)(sm + HBIAS_OFF);
        const int cb = (lane & 3) * 2;
        const int r_lo = row0 + rowb + (lane >> 2);
        const int r_hi = r_lo + 8;

#pragma unroll
        for (int g8 = 0; g8 < 8; g8++) {
            uint32_t Bi[4], Bg[4], Bo[4];
            ldsm4(b_base + (uint32_t)((g8 * 8) * 48), Bi);
            ldsm4(b_base + (uint32_t)((64 + g8 * 8) * 48), Bg);
            ldsm4(b_base + (uint32_t)((128 + g8 * 8) * 48), Bo);

            int u0 = g8 * 8 + cb;
            float bi0 = bs[u0],       bi1 = bs[u0 + 1];
            float bg0 = bs[64 + u0],  bg1 = bs[64 + u0 + 1];
            float bo0 = bs[128 + u0], bo1 = bs[128 + u0 + 1];
            float ai[4] = {bi0, bi1, bi0, bi1};
            float ag[4] = {bg0, bg1, bg0, bg1};
            float ao[4] = {bo0, bo1, bo0, bo1};

            mma_f16(ai, A0, Bi[0], Bi[1]);  mma_f16(ai, A1, Bi[2], Bi[3]);
            mma_f16(ag, A0, Bg[0], Bg[1]);  mma_f16(ag, A1, Bg[2], Bg[3]);
            mma_f16(ao, A0, Bo[0], Bo[1]);  mma_f16(ao, A1, Bo[2], Bo[3]);

            float h0 = sig_t(ao[0]) * tanhf(sig_t(ai[0]) * tanhf(ag[0]));
            float h1 = sig_t(ao[1]) * tanhf(sig_t(ai[1]) * tanhf(ag[1]));
            float h2 = sig_t(ao[2]) * tanhf(sig_t(ai[2]) * tanhf(ag[2]));
            float h3 = sig_t(ao[3]) * tanhf(sig_t(ai[3]) * tanhf(ag[3]));

            if (r_lo < N)
                *(__half2*)(g_hf + (size_t)r_lo * HID + u0) = __floats2half2_rn(h0, h1);
            if (r_hi < N)
                *(__half2*)(g_hf + (size_t)r_hi * HID + u0) = __floats2half2_rn(h2, h3);
        }
    }
}

// ---------------- gemm kernel: fp16 mma.sync + odd-strip copy blocks ----------------
// group g of 14 blocks: r<12 -> gemm (strip 2g + r/6, sub r%6); r>=12 -> copy
// odd strip 2g+1, half (r-12).
// smem: A[kc(4)][r(128)][48B], B[kc(4)][n(128)][48B], bias
#define KCB 6144    // 128*48
#define A_OFF 0
#define B_OFF 24576
#define S_BIAS 49152
#define GEMM_SMEM 49664

__global__ __launch_bounds__(256, 2)
void gemm_kernel(const float* __restrict__ b_fc,
                 const float* __restrict__ CC,
                 float* __restrict__ cc_out,
                 float* __restrict__ vs_out,
                 int N)
{
    extern __shared__ char sm[];
    const int t = threadIdx.x;
    const int bid = blockIdx.x;
    const int grp = bid / 14, r14 = bid % 14;

    // ---- copy blocks: odd strip, 64 rows each ----
    if (r14 >= 12) {
        int row0 = (2 * grp + 1) * MTILE + (r14 - 12) * 64;
        if (row0 >= N) return;
        const float4* src = (const float4*)(CC + (size_t)row0 * OUTF);
        float4* dst = (float4*)(cc_out + (size_t)row0 * OUTF);
        if (row0 + 64 <= N) {
            // 64*768/4 = 12288 = 6 batches * 8 * 256
#pragma unroll 1
            for (int it = 0; it < 6; it++) {
                int base = it * 2048 + t;
                float4 buf[8];
#pragma unroll
                for (int j = 0; j < 8; j++) buf[j] = src[base + j * 256];
#pragma unroll
                for (int j = 0; j < 8; j++) dst[base + j * 256] = buf[j];
            }
        } else {
            int total = (N - row0) * (OUTF / 4);
            for (int i = t; i < total; i += 256) dst[i] = src[i];
        }
        return;
    }

    const int sub = r14 % 6;
    const int row0 = (2 * grp + r14 / 6) * MTILE;
    if (row0 >= N) return;

    const int lane = t & 31;
    const int wm = t >> 5;
    const int ctb = sub * NTILE;
    const uint32_t sb = smem_u32(sm);

    // bias
    if (t < 32) ((float4*)(sm + S_BIAS))[t] = ((const float4*)(b_fc + ctb))[t];

    // A fill
#pragma unroll
    for (int j = 0; j < 4; j++) {
        int i = t + j * 256;
        int r = i >> 3, q = i & 7;
        int kc = q >> 1, hf = q & 1;
        uint4 v = make_uint4(0, 0, 0, 0);
        if (row0 + r < N)
            v = ((const uint4*)(g_hf + (size_t)(row0 + r) * HID))[q];
        *(uint4*)(sm + A_OFF + kc * KCB + r * 48 + hf * 16) = v;
    }
    // B fill
#pragma unroll
    for (int j = 0; j < 4; j++) {
        int i = t + j * 256;
        int n = i >> 3, q = i & 7;
        int kc = q >> 1, hf = q & 1;
        *(uint4*)(sm + B_OFF + kc * KCB + n * 48 + hf * 16) =
            ((const uint4*)(g_wf + (size_t)(ctb + n) * HID))[q];
    }
    __syncthreads();

    float acc[16][4];
    {
        const float* bs = (const float*)(sm + S_BIAS);
        int cb = (lane & 3) * 2;
#pragma unroll
        for (int nt = 0; nt < 16; nt++) {
            float b0 = bs[nt * 8 + cb], b1 = bs[nt * 8 + cb + 1];
            acc[nt][0] = b0; acc[nt][1] = b1; acc[nt][2] = b0; acc[nt][3] = b1;
        }
    }

    const int rowb = wm * 16;
    const uint32_t a_lane_off = (uint32_t)((rowb + (lane & 15)) * 48 + ((lane & 16) ? 16 : 0));
    const uint32_t b_row_off  = (uint32_t)((lane & 7) * 48 + ((lane & 8) ? 16 : 0));
    const uint32_t b_kc_sel   = (uint32_t)(((lane >> 4) & 1) * KCB);

#pragma unroll
    for (int p = 0; p < 2; p++) {
        uint32_t A[2][4];
#pragma unroll
        for (int j = 0; j < 2; j++)
            ldsm4(sb + A_OFF + (2 * p + j) * KCB + a_lane_off, A[j]);
#pragma unroll
        for (int nt = 0; nt < 16; nt++) {
            uint32_t B[4];
            uint32_t boff = 2 * p * KCB + b_kc_sel + (uint32_t)(nt * 8 * 48) + b_row_off;
            ldsm4(sb + B_OFF + boff, B);
            mma_f16(acc[nt], A[0], B[0], B[1]);
            mma_f16(acc[nt], A[1], B[2], B[3]);
        }
    }

    {
        int r_lo = row0 + rowb + (lane >> 2);
        int r_hi = r_lo + 8;
        int cb = ctb + (lane & 3) * 2;
#pragma unroll
        for (int nt = 0; nt < 16; nt++) {
            if (r_lo < N)
                *(float2*)(vs_out + (size_t)r_lo * OUTF + cb + nt * 8) =
                    make_float2(acc[nt][0], acc[nt][1]);
            if (r_hi < N)
                *(float2*)(vs_out + (size_t)r_hi * OUTF + cb + nt * 8) =
                    make_float2(acc[nt][2], acc[nt][3]);
        }
    }
}

extern "C" void kernel_launch(void* const* d_in, const int* in_sizes, int n_in,
                              void* d_out, int out_size) {
    const float* VS     = (const float*)d_in[0];
    const float* CC     = (const float*)d_in[1];
    const int*   Level  = (const int*)d_in[2];
    const int*   Depart = (const int*)d_in[3];
    const float* W_ih   = (const float*)d_in[4];
    // d_in[5] = W_hh, unused (h0 = 0)
    const float* b_ih   = (const float*)d_in[6];
    const float* b_hh   = (const float*)d_in[7];
    const float* W_fc   = (const float*)d_in[8];
    const float* b_fc   = (const float*)d_in[9];

    int N = in_sizes[0] / NF;

    float* out = (float*)d_out;
    float* cc_out  = out;
    float* vs_out  = out + (size_t)N * OUTF;
    float* lev_out = out + (size_t)2 * N * OUTF;
    float* dep_out = lev_out + N;

    static int attr_set = 0;
    if (!attr_set) {
        cudaFuncSetAttribute(h_kernel,
                             cudaFuncAttributeMaxDynamicSharedMemorySize, HK_SMEM);
        cudaFuncSetAttribute(gemm_kernel,
                             cudaFuncAttributeMaxDynamicSharedMemorySize, GEMM_SMEM);
        attr_set = 1;
    }

    hist_all_kernel<<<HIST_BLOCKS, 256>>>(VS, Level, W_fc, W_ih, b_ih, b_hh, N);
    int nstrip = (N + MTILE - 1) / MTILE;
    int ngrp = (nstrip + 1) / 2;
    h_kernel<<<ngrp * 3, 256, HK_SMEM>>>(
        VS, Level, Depart, CC, cc_out, lev_out, dep_out, N);
    gemm_kernel<<<ngrp * 14, 256, GEMM_SMEM>>>(b_fc, CC, cc_out, vs_out, N);
}